// round 16
// baseline (speedup 1.0000x reference)
#include <cuda_runtime.h>
#include <math.h>
#include <stdint.h>
#include <limits.h>

#define BATCH 4
#define SEQ   4096
#define DIM   256
#define TOPK  32
#define ROWS  (BATCH*SEQ)
#define BK    8
#define QS    20.0f          // int8 quant scale

#define FULLM 0xffffffffu

// ---------------- device scratch (allocation-free contract) ----------------
__device__ float    g_q[ROWS*DIM];
__device__ float    g_k[ROWS*DIM];
__device__ float    g_v[ROWS*DIM];
__device__ uint32_t g_q8[ROWS*(DIM/4)];   // packed int8 (signed bytes)
__device__ uint32_t g_k8[ROWS*(DIM/4)];
__device__ short    g_ss[(size_t)BATCH*SEQ*SEQ];   // 134 MB int16 scores
__device__ int      g_cnt[BATCH][32];     // per (batch, q-tile-row) tile counters
__device__ int      g_vcnt;               // vproj completion counter

__device__ __forceinline__ uint32_t pack4(float a, float b, float c, float d)
{
    int ia = __float2int_rn(fminf(fmaxf(a*QS, -127.f), 127.f));
    int ib = __float2int_rn(fminf(fmaxf(b*QS, -127.f), 127.f));
    int ic = __float2int_rn(fminf(fmaxf(c*QS, -127.f), 127.f));
    int id = __float2int_rn(fminf(fmaxf(d*QS, -127.f), 127.f));
    return (uint32_t)(ia & 0xff) | ((uint32_t)(ib & 0xff) << 8)
         | ((uint32_t)(ic & 0xff) << 16) | ((uint32_t)(id & 0xff) << 24);
}

// ---------------------------------------------------------------------------
// Kernel 0: zero the sync counters (each graph replay).
// ---------------------------------------------------------------------------
__global__ void zero_kernel()
{
    const int t = threadIdx.x;
    if (t < BATCH*32) ((int*)g_cnt)[t] = 0;
    if (t == BATCH*32) g_vcnt = 0;
}

// ---------------------------------------------------------------------------
// Kernel 1: q,k projections only (z=2), R8 pipeline + int8 quant.
// ---------------------------------------------------------------------------
__global__ __launch_bounds__(256, 2)
void qkv_kernel(const float* __restrict__ x,
                const float* __restrict__ Wq, const float* __restrict__ bq,
                const float* __restrict__ Wk, const float* __restrict__ bk)
{
    __shared__ float As[2][BK*128];
    __shared__ float Bs[2][BK*128];

    const int which = blockIdx.z;             // 0=q, 1=k
    const float* W    = (which==0) ? Wq : Wk;
    const float* bias = (which==0) ? bq : bk;
    float* outp       = (which==0) ? g_q : g_k;

    const int tid = threadIdx.x;
    const int tx = tid & 15, ty = tid >> 4;
    const int row0 = blockIdx.x * 128;
    const int col0 = blockIdx.y * 128;

    float acc[8][8];
    #pragma unroll
    for (int i = 0; i < 8; i++)
        #pragma unroll
        for (int j = 0; j < 8; j++) acc[i][j] = 0.f;

    const int amm = tid >> 1;
    const int akk = (tid & 1) * 4;
    const int bkk = tid >> 5;
    const int bnn = (tid & 31) * 4;

    const int NST = DIM / BK;
    float4 rA, rB;

    rA = *(const float4*)&x[(size_t)(row0 + amm)*DIM + akk];
    rB = *(const float4*)&W[(size_t)bkk*DIM + col0 + bnn];
    As[0][(akk+0)*128 + amm] = rA.x;
    As[0][(akk+1)*128 + amm] = rA.y;
    As[0][(akk+2)*128 + amm] = rA.z;
    As[0][(akk+3)*128 + amm] = rA.w;
    *(float4*)&Bs[0][bkk*128 + bnn] = rB;
    __syncthreads();

    for (int s = 0; s < NST; s++) {
        if (s + 1 < NST) {
            const int k0 = (s+1) * BK;
            rA = *(const float4*)&x[(size_t)(row0 + amm)*DIM + k0 + akk];
            rB = *(const float4*)&W[(size_t)(k0 + bkk)*DIM + col0 + bnn];
        }
        const float* Ac = As[s & 1];
        const float* Bc = Bs[s & 1];
        #pragma unroll
        for (int kk = 0; kk < BK; kk++) {
            float a[8], b[8];
            *(float4*)&a[0] = *(const float4*)&Ac[kk*128 + ty*8];
            *(float4*)&a[4] = *(const float4*)&Ac[kk*128 + ty*8 + 4];
            *(float4*)&b[0] = *(const float4*)&Bc[kk*128 + tx*8];
            *(float4*)&b[4] = *(const float4*)&Bc[kk*128 + tx*8 + 4];
            #pragma unroll
            for (int i = 0; i < 8; i++)
                #pragma unroll
                for (int j = 0; j < 8; j++)
                    acc[i][j] = fmaf(a[i], b[j], acc[i][j]);
        }
        if (s + 1 < NST) {
            float* An = As[(s+1) & 1];
            An[(akk+0)*128 + amm] = rA.x;
            An[(akk+1)*128 + amm] = rA.y;
            An[(akk+2)*128 + amm] = rA.z;
            An[(akk+3)*128 + amm] = rA.w;
            *(float4*)&Bs[(s+1) & 1][bkk*128 + bnn] = rB;
            __syncthreads();
        }
    }

    uint32_t* o8 = (which==0) ? g_q8 : g_k8;
    #pragma unroll
    for (int i = 0; i < 8; i++) {
        const int r = row0 + ty*8 + i;
        float v[8];
        #pragma unroll
        for (int j = 0; j < 8; j++) v[j] = acc[i][j] + bias[col0 + tx*8 + j];
        *(float4*)&outp[(size_t)r*DIM + col0 + tx*8]     = *(float4*)&v[0];
        *(float4*)&outp[(size_t)r*DIM + col0 + tx*8 + 4] = *(float4*)&v[4];
        uint2 pk;
        pk.x = pack4(v[0], v[1], v[2], v[3]);
        pk.y = pack4(v[4], v[5], v[6], v[7]);
        *(uint2*)&o8[(size_t)r*(DIM/4) + col0/4 + tx*2] = pk;
    }
}

// ---------------------------------------------------------------------------
// Kernel 2 (mega): z=0 vproj; z odd -> scores batch (z-1)/2 (+counter bump);
// z even>=2 -> select batch (z-2)/2 (spins on counters, then scan/rescore/AV).
// grid = (32, 32, 9), 256 threads, 2 CTAs/SM.
// ---------------------------------------------------------------------------
__global__ __launch_bounds__(256, 2)
void mega_kernel(const float* __restrict__ x,
                 const float* __restrict__ Wv, const float* __restrict__ bv,
                 float* __restrict__ out)
{
    __shared__ __align__(16) char smraw[16384];

    const int tid = threadIdx.x;
    const int tx = tid & 15, ty = tid >> 4;

    if (blockIdx.z == 0) {
        // ---------------- v projection path ----------------
        const int idx = blockIdx.y * 32 + blockIdx.x;
        if (idx >= (ROWS/128) * (DIM/128)) return;   // 256 live blocks
        const int row0 = (idx >> 1) * 128;
        const int col0 = (idx & 1)  * 128;

        float* As = (float*)smraw;
        float* Bs = (float*)smraw + 2*BK*128;

        float acc[8][8];
        #pragma unroll
        for (int i = 0; i < 8; i++)
            #pragma unroll
            for (int j = 0; j < 8; j++) acc[i][j] = 0.f;

        const int amm = tid >> 1;
        const int akk = (tid & 1) * 4;
        const int bkk = tid >> 5;
        const int bnn = (tid & 31) * 4;

        const int NST = DIM / BK;
        float4 rA, rB;

        rA = *(const float4*)&x[(size_t)(row0 + amm)*DIM + akk];
        rB = *(const float4*)&Wv[(size_t)bkk*DIM + col0 + bnn];
        As[(akk+0)*128 + amm] = rA.x;
        As[(akk+1)*128 + amm] = rA.y;
        As[(akk+2)*128 + amm] = rA.z;
        As[(akk+3)*128 + amm] = rA.w;
        *(float4*)&Bs[bkk*128 + bnn] = rB;
        __syncthreads();

        for (int s = 0; s < NST; s++) {
            if (s + 1 < NST) {
                const int k0 = (s+1) * BK;
                rA = *(const float4*)&x[(size_t)(row0 + amm)*DIM + k0 + akk];
                rB = *(const float4*)&Wv[(size_t)(k0 + bkk)*DIM + col0 + bnn];
            }
            const float* Ac = As + (s & 1)*BK*128;
            const float* Bc = Bs + (s & 1)*BK*128;
            #pragma unroll
            for (int kk = 0; kk < BK; kk++) {
                float a[8], b[8];
                *(float4*)&a[0] = *(const float4*)&Ac[kk*128 + ty*8];
                *(float4*)&a[4] = *(const float4*)&Ac[kk*128 + ty*8 + 4];
                *(float4*)&b[0] = *(const float4*)&Bc[kk*128 + tx*8];
                *(float4*)&b[4] = *(const float4*)&Bc[kk*128 + tx*8 + 4];
                #pragma unroll
                for (int i = 0; i < 8; i++)
                    #pragma unroll
                    for (int j = 0; j < 8; j++)
                        acc[i][j] = fmaf(a[i], b[j], acc[i][j]);
            }
            if (s + 1 < NST) {
                float* An = As + ((s+1) & 1)*BK*128;
                An[(akk+0)*128 + amm] = rA.x;
                An[(akk+1)*128 + amm] = rA.y;
                An[(akk+2)*128 + amm] = rA.z;
                An[(akk+3)*128 + amm] = rA.w;
                *(float4*)&Bs[((s+1) & 1)*BK*128 + bkk*128 + bnn] = rB;
                __syncthreads();
            }
        }

        #pragma unroll
        for (int i = 0; i < 8; i++) {
            const int r = row0 + ty*8 + i;
            #pragma unroll
            for (int j = 0; j < 8; j += 4) {
                const int c = col0 + tx*8 + j;
                float4 o;
                o.x = acc[i][j+0] + bv[c+0];
                o.y = acc[i][j+1] + bv[c+1];
                o.z = acc[i][j+2] + bv[c+2];
                o.w = acc[i][j+3] + bv[c+3];
                *(float4*)&g_v[(size_t)r*DIM + c] = o;
            }
        }
        __threadfence();
        __syncthreads();
        if (tid == 0) atomicAdd(&g_vcnt, 1);
        return;
    }

    if (blockIdx.z & 1) {
        // ---------------- int8 score GEMM path (batch b) ----------------
        int* As8 = (int*)smraw;          // [2][8*128]
        int* Bs8 = (int*)smraw + 2048;

        const int b   = (blockIdx.z - 1) >> 1;
        const int k0t = blockIdx.x * 128;
        const int q0t = blockIdx.y * 128;
        const uint32_t* q8 = g_q8 + (size_t)b*SEQ*(DIM/4);
        const uint32_t* k8 = g_k8 + (size_t)b*SEQ*(DIM/4);

        int acc[8][8];
        #pragma unroll
        for (int i = 0; i < 8; i++)
            #pragma unroll
            for (int j = 0; j < 8; j++) acc[i][j] = 0;

        const int amm = tid >> 1;
        const int au  = (tid & 1) * 4;

        const int NST = 8;
        uint4 rA, rB;

        rA = *(const uint4*)&q8[(size_t)(q0t + amm)*(DIM/4) + au];
        rB = *(const uint4*)&k8[(size_t)(k0t + amm)*(DIM/4) + au];
        As8[(au+0)*128 + amm] = (int)rA.x;
        As8[(au+1)*128 + amm] = (int)rA.y;
        As8[(au+2)*128 + amm] = (int)rA.z;
        As8[(au+3)*128 + amm] = (int)rA.w;
        Bs8[(au+0)*128 + amm] = (int)rB.x;
        Bs8[(au+1)*128 + amm] = (int)rB.y;
        Bs8[(au+2)*128 + amm] = (int)rB.z;
        Bs8[(au+3)*128 + amm] = (int)rB.w;
        __syncthreads();

        for (int s = 0; s < NST; s++) {
            if (s + 1 < NST) {
                rA = *(const uint4*)&q8[(size_t)(q0t + amm)*(DIM/4) + (s+1)*8 + au];
                rB = *(const uint4*)&k8[(size_t)(k0t + amm)*(DIM/4) + (s+1)*8 + au];
            }
            const int* Ac = As8 + (s & 1)*1024;
            const int* Bc = Bs8 + (s & 1)*1024;
            #pragma unroll
            for (int pk = 0; pk < 8; pk++) {
                int a[8], bb[8];
                *(int4*)&a[0]  = *(const int4*)&Ac[pk*128 + ty*8];
                *(int4*)&a[4]  = *(const int4*)&Ac[pk*128 + ty*8 + 4];
                *(int4*)&bb[0] = *(const int4*)&Bc[pk*128 + tx*8];
                *(int4*)&bb[4] = *(const int4*)&Bc[pk*128 + tx*8 + 4];
                #pragma unroll
                for (int i = 0; i < 8; i++)
                    #pragma unroll
                    for (int j = 0; j < 8; j++)
                        acc[i][j] = __dp4a(a[i], bb[j], acc[i][j]);
            }
            if (s + 1 < NST) {
                int* An = As8 + ((s+1) & 1)*1024;
                int* Bn = Bs8 + ((s+1) & 1)*1024;
                An[(au+0)*128 + amm] = (int)rA.x;
                An[(au+1)*128 + amm] = (int)rA.y;
                An[(au+2)*128 + amm] = (int)rA.z;
                An[(au+3)*128 + amm] = (int)rA.w;
                Bn[(au+0)*128 + amm] = (int)rB.x;
                Bn[(au+1)*128 + amm] = (int)rB.y;
                Bn[(au+2)*128 + amm] = (int)rB.z;
                Bn[(au+3)*128 + amm] = (int)rB.w;
                __syncthreads();
            }
        }

        short* srow = g_ss + ((size_t)b*SEQ + q0t)*SEQ + k0t;
        #pragma unroll
        for (int i = 0; i < 8; i++) {
            uint32_t w[4];
            #pragma unroll
            for (int j2 = 0; j2 < 4; j2++) {
                int v0 = acc[i][j2*2+0], v1 = acc[i][j2*2+1];
                v0 = v0 > 32767 ? 32767 : (v0 < -32768 ? -32768 : v0);
                v1 = v1 > 32767 ? 32767 : (v1 < -32768 ? -32768 : v1);
                w[j2] = (uint32_t)(v0 & 0xffff) | ((uint32_t)v1 << 16);
            }
            *(uint4*)&srow[(size_t)(ty*8 + i)*SEQ + tx*8] = *(uint4*)w;
        }
        __threadfence();
        __syncthreads();
        if (tid == 0) atomicAdd(&g_cnt[b][blockIdx.y], 1);
        return;
    }

    // ---------------- select path (batch b, spins on producers) ----------------
    {
        const int b    = (blockIdx.z - 2) >> 1;
        const int cidx = blockIdx.y * 32 + blockIdx.x;
        if (cidx >= 512) return;                 // 512 live CTAs, 8 queries each
        const int qt   = cidx >> 4;              // q-tile row (128 queries)

        if (tid == 0) {
            while (*(volatile int*)&g_cnt[b][qt] != 32 ||
                   *(volatile int*)&g_vcnt != 256)
                __nanosleep(64);
        }
        __syncthreads();
        __threadfence();

        const int lane = tid & 31;
        const int q    = cidx * 8 + (tid >> 5);

        int myval = INT_MIN;
        int myidx = 0;

        const uint4* srow = (const uint4*)(g_ss + ((size_t)b*SEQ + q)*SEQ);

        uint4 u = __ldcs(&srow[lane]);
        #pragma unroll 1
        for (int i = 0; i < SEQ/256; i++) {
            uint4 cur = u;
            if (i + 1 < SEQ/256)
                u = __ldcs(&srow[(i+1)*32 + lane]);
            int sv[8];
            sv[0] = (int)(short)(cur.x);  sv[1] = (int)(short)(cur.x >> 16);
            sv[2] = (int)(short)(cur.y);  sv[3] = (int)(short)(cur.y >> 16);
            sv[4] = (int)(short)(cur.z);  sv[5] = (int)(short)(cur.z >> 16);
            sv[6] = (int)(short)(cur.w);  sv[7] = (int)(short)(cur.w >> 16);
            int thr = __shfl_sync(FULLM, myval, 31);
            bool cand = false;
            #pragma unroll
            for (int t = 0; t < 8; t++) cand |= (sv[t] > thr);
            if (__any_sync(FULLM, cand)) {
                #pragma unroll
                for (int t = 0; t < 8; t++) {
                    int v = sv[t];
                    thr = __shfl_sync(FULLM, myval, 31);
                    unsigned cm = __ballot_sync(FULLM, v > thr);
                    while (cm) {
                        int src = __ffs(cm) - 1;
                        cm &= cm - 1;
                        int bv2  = __shfl_sync(FULLM, v, src);
                        int bidx = i*256 + src*8 + t;
                        bool gt = bv2 > myval;
                        unsigned bm = __ballot_sync(FULLM, gt);
                        int upv = __shfl_up_sync(FULLM, myval, 1);
                        int upi = __shfl_up_sync(FULLM, myidx, 1);
                        if (bm) {
                            int p = __ffs(bm) - 1;
                            if (gt) {
                                myval = (lane == p) ? bv2 : upv;
                                myidx = (lane == p) ? bidx : upi;
                            }
                        }
                    }
                }
            }
        }

        // exact fp32 rescore of the 32 selected keys
        const float4* qr = (const float4*)(g_q + ((size_t)b*SEQ + q)*DIM);
        float4 q0v = qr[lane*2], q1v = qr[lane*2 + 1];
        float myex = 0.f;
        #pragma unroll 4
        for (int j = 0; j < TOPK; j++) {
            int ij = __shfl_sync(FULLM, myidx, j);
            const float4* kr = (const float4*)(g_k + ((size_t)b*SEQ + ij)*DIM);
            float4 k0v = kr[lane*2], k1v = kr[lane*2 + 1];
            float d = q0v.x*k0v.x;
            d = fmaf(q0v.y, k0v.y, d);
            d = fmaf(q0v.z, k0v.z, d);
            d = fmaf(q0v.w, k0v.w, d);
            d = fmaf(q1v.x, k1v.x, d);
            d = fmaf(q1v.y, k1v.y, d);
            d = fmaf(q1v.z, k1v.z, d);
            d = fmaf(q1v.w, k1v.w, d);
            #pragma unroll
            for (int o = 16; o; o >>= 1) d += __shfl_xor_sync(FULLM, d, o);
            if (lane == j) myex = d;
        }

        float mx = myex;
        #pragma unroll
        for (int o = 16; o; o >>= 1) mx = fmaxf(mx, __shfl_xor_sync(FULLM, mx, o));
        float e = expf(myex - mx);
        float ssum = e;
        #pragma unroll
        for (int o = 16; o; o >>= 1) ssum += __shfl_xor_sync(FULLM, ssum, o);
        float p = e / ssum;

        const float4* vb = (const float4*)(g_v + (size_t)b*SEQ*DIM);
        float4 a0 = make_float4(0.f,0.f,0.f,0.f);
        float4 a1 = make_float4(0.f,0.f,0.f,0.f);
        #pragma unroll 4
        for (int j = 0; j < TOPK; j++) {
            float pj = __shfl_sync(FULLM, p, j);
            int   ij = __shfl_sync(FULLM, myidx, j);
            float4 v0 = vb[(size_t)ij*64 + lane*2];
            float4 v1 = vb[(size_t)ij*64 + lane*2 + 1];
            a0.x = fmaf(pj, v0.x, a0.x);
            a0.y = fmaf(pj, v0.y, a0.y);
            a0.z = fmaf(pj, v0.z, a0.z);
            a0.w = fmaf(pj, v0.w, a0.w);
            a1.x = fmaf(pj, v1.x, a1.x);
            a1.y = fmaf(pj, v1.y, a1.y);
            a1.z = fmaf(pj, v1.z, a1.z);
            a1.w = fmaf(pj, v1.w, a1.w);
        }
        float4* ob = (float4*)(out + ((size_t)b*SEQ + q)*DIM);
        ob[lane*2]     = a0;
        ob[lane*2 + 1] = a1;
    }
}

extern "C" void kernel_launch(void* const* d_in, const int* in_sizes, int n_in,
                              void* d_out, int out_size)
{
    const float* x  = (const float*)d_in[0];
    const float* Wq = (const float*)d_in[1];
    const float* bq = (const float*)d_in[2];
    const float* Wk = (const float*)d_in[3];
    const float* bk = (const float*)d_in[4];
    const float* Wv = (const float*)d_in[5];
    const float* bv = (const float*)d_in[6];
    float* out = (float*)d_out;

    zero_kernel<<<1, 160>>>();

    dim3 g1(ROWS/128, DIM/128, 2);            // q,k only
    qkv_kernel<<<g1, 256>>>(x, Wq, bq, Wk, bk);

    // z=0: vproj; z=1,3,5,7: scores b0..b3; z=2,4,6,8: select b0..b3
    dim3 g2(32, 32, 2*BATCH + 1);
    mega_kernel<<<g2, 256>>>(x, Wv, bv, out);
}

// round 17
// speedup vs baseline: 1.0202x; 1.0202x over previous
#include <cuda_runtime.h>
#include <math.h>
#include <stdint.h>
#include <limits.h>

#define BATCH 4
#define SEQ   4096
#define DIM   256
#define TOPK  32
#define ROWS  (BATCH*SEQ)
#define BK    8
#define QS    20.0f          // int8 quant scale

#define FULLM 0xffffffffu

// ---------------- device scratch (allocation-free contract) ----------------
__device__ float    g_q[ROWS*DIM];
__device__ float    g_k[ROWS*DIM];
__device__ float    g_v[ROWS*DIM];
__device__ uint32_t g_q8[ROWS*(DIM/4)];   // packed int8 (signed bytes)
__device__ uint32_t g_k8[ROWS*(DIM/4)];
__device__ short    g_ss[(size_t)BATCH*SEQ*SEQ];   // 134 MB int16 scores

__device__ __forceinline__ uint32_t pack4(float a, float b, float c, float d)
{
    int ia = __float2int_rn(fminf(fmaxf(a*QS, -127.f), 127.f));
    int ib = __float2int_rn(fminf(fmaxf(b*QS, -127.f), 127.f));
    int ic = __float2int_rn(fminf(fmaxf(c*QS, -127.f), 127.f));
    int id = __float2int_rn(fminf(fmaxf(d*QS, -127.f), 127.f));
    return (uint32_t)(ia & 0xff) | ((uint32_t)(ib & 0xff) << 8)
         | ((uint32_t)(ic & 0xff) << 16) | ((uint32_t)(id & 0xff) << 24);
}

// ---------------------------------------------------------------------------
// Kernel 1: q,k projections only (z=2), R8 pipeline + int8 quant.
// ---------------------------------------------------------------------------
__global__ __launch_bounds__(256, 2)
void qkv_kernel(const float* __restrict__ x,
                const float* __restrict__ Wq, const float* __restrict__ bq,
                const float* __restrict__ Wk, const float* __restrict__ bk)
{
    __shared__ float As[2][BK*128];
    __shared__ float Bs[2][BK*128];

    const int which = blockIdx.z;             // 0=q, 1=k
    const float* W    = (which==0) ? Wq : Wk;
    const float* bias = (which==0) ? bq : bk;
    float* outp       = (which==0) ? g_q : g_k;

    const int tid = threadIdx.x;
    const int tx = tid & 15, ty = tid >> 4;
    const int row0 = blockIdx.x * 128;
    const int col0 = blockIdx.y * 128;

    float acc[8][8];
    #pragma unroll
    for (int i = 0; i < 8; i++)
        #pragma unroll
        for (int j = 0; j < 8; j++) acc[i][j] = 0.f;

    const int amm = tid >> 1;
    const int akk = (tid & 1) * 4;
    const int bkk = tid >> 5;
    const int bnn = (tid & 31) * 4;

    const int NST = DIM / BK;
    float4 rA, rB;

    rA = *(const float4*)&x[(size_t)(row0 + amm)*DIM + akk];
    rB = *(const float4*)&W[(size_t)bkk*DIM + col0 + bnn];
    As[0][(akk+0)*128 + amm] = rA.x;
    As[0][(akk+1)*128 + amm] = rA.y;
    As[0][(akk+2)*128 + amm] = rA.z;
    As[0][(akk+3)*128 + amm] = rA.w;
    *(float4*)&Bs[0][bkk*128 + bnn] = rB;
    __syncthreads();

    for (int s = 0; s < NST; s++) {
        if (s + 1 < NST) {
            const int k0 = (s+1) * BK;
            rA = *(const float4*)&x[(size_t)(row0 + amm)*DIM + k0 + akk];
            rB = *(const float4*)&W[(size_t)(k0 + bkk)*DIM + col0 + bnn];
        }
        const float* Ac = As[s & 1];
        const float* Bc = Bs[s & 1];
        #pragma unroll
        for (int kk = 0; kk < BK; kk++) {
            float a[8], b[8];
            *(float4*)&a[0] = *(const float4*)&Ac[kk*128 + ty*8];
            *(float4*)&a[4] = *(const float4*)&Ac[kk*128 + ty*8 + 4];
            *(float4*)&b[0] = *(const float4*)&Bc[kk*128 + tx*8];
            *(float4*)&b[4] = *(const float4*)&Bc[kk*128 + tx*8 + 4];
            #pragma unroll
            for (int i = 0; i < 8; i++)
                #pragma unroll
                for (int j = 0; j < 8; j++)
                    acc[i][j] = fmaf(a[i], b[j], acc[i][j]);
        }
        if (s + 1 < NST) {
            float* An = As[(s+1) & 1];
            An[(akk+0)*128 + amm] = rA.x;
            An[(akk+1)*128 + amm] = rA.y;
            An[(akk+2)*128 + amm] = rA.z;
            An[(akk+3)*128 + amm] = rA.w;
            *(float4*)&Bs[(s+1) & 1][bkk*128 + bnn] = rB;
            __syncthreads();
        }
    }

    uint32_t* o8 = (which==0) ? g_q8 : g_k8;
    #pragma unroll
    for (int i = 0; i < 8; i++) {
        const int r = row0 + ty*8 + i;
        float v[8];
        #pragma unroll
        for (int j = 0; j < 8; j++) v[j] = acc[i][j] + bias[col0 + tx*8 + j];
        *(float4*)&outp[(size_t)r*DIM + col0 + tx*8]     = *(float4*)&v[0];
        *(float4*)&outp[(size_t)r*DIM + col0 + tx*8 + 4] = *(float4*)&v[4];
        uint2 pk;
        pk.x = pack4(v[0], v[1], v[2], v[3]);
        pk.y = pack4(v[4], v[5], v[6], v[7]);
        *(uint2*)&o8[(size_t)r*(DIM/4) + col0/4 + tx*2] = pk;
    }
}

// ---------------------------------------------------------------------------
// device paths (R15-validated bodies)
// ---------------------------------------------------------------------------
__device__ __forceinline__ void vproj_path(char* smraw,
    const float* __restrict__ x, const float* __restrict__ Wv,
    const float* __restrict__ bv)
{
    const int tid = threadIdx.x;
    const int tx = tid & 15, ty = tid >> 4;
    const int idx = blockIdx.y * 32 + blockIdx.x;
    if (idx >= (ROWS/128) * (DIM/128)) return;   // 256 live blocks
    const int row0 = (idx >> 1) * 128;
    const int col0 = (idx & 1)  * 128;

    float* As = (float*)smraw;
    float* Bs = (float*)smraw + 2*BK*128;

    float acc[8][8];
    #pragma unroll
    for (int i = 0; i < 8; i++)
        #pragma unroll
        for (int j = 0; j < 8; j++) acc[i][j] = 0.f;

    const int amm = tid >> 1;
    const int akk = (tid & 1) * 4;
    const int bkk = tid >> 5;
    const int bnn = (tid & 31) * 4;

    const int NST = DIM / BK;
    float4 rA, rB;

    rA = *(const float4*)&x[(size_t)(row0 + amm)*DIM + akk];
    rB = *(const float4*)&Wv[(size_t)bkk*DIM + col0 + bnn];
    As[(akk+0)*128 + amm] = rA.x;
    As[(akk+1)*128 + amm] = rA.y;
    As[(akk+2)*128 + amm] = rA.z;
    As[(akk+3)*128 + amm] = rA.w;
    *(float4*)&Bs[bkk*128 + bnn] = rB;
    __syncthreads();

    for (int s = 0; s < NST; s++) {
        if (s + 1 < NST) {
            const int k0 = (s+1) * BK;
            rA = *(const float4*)&x[(size_t)(row0 + amm)*DIM + k0 + akk];
            rB = *(const float4*)&Wv[(size_t)(k0 + bkk)*DIM + col0 + bnn];
        }
        const float* Ac = As + (s & 1)*BK*128;
        const float* Bc = Bs + (s & 1)*BK*128;
        #pragma unroll
        for (int kk = 0; kk < BK; kk++) {
            float a[8], b[8];
            *(float4*)&a[0] = *(const float4*)&Ac[kk*128 + ty*8];
            *(float4*)&a[4] = *(const float4*)&Ac[kk*128 + ty*8 + 4];
            *(float4*)&b[0] = *(const float4*)&Bc[kk*128 + tx*8];
            *(float4*)&b[4] = *(const float4*)&Bc[kk*128 + tx*8 + 4];
            #pragma unroll
            for (int i = 0; i < 8; i++)
                #pragma unroll
                for (int j = 0; j < 8; j++)
                    acc[i][j] = fmaf(a[i], b[j], acc[i][j]);
        }
        if (s + 1 < NST) {
            float* An = As + ((s+1) & 1)*BK*128;
            An[(akk+0)*128 + amm] = rA.x;
            An[(akk+1)*128 + amm] = rA.y;
            An[(akk+2)*128 + amm] = rA.z;
            An[(akk+3)*128 + amm] = rA.w;
            *(float4*)&Bs[((s+1) & 1)*BK*128 + bkk*128 + bnn] = rB;
            __syncthreads();
        }
    }

    #pragma unroll
    for (int i = 0; i < 8; i++) {
        const int r = row0 + ty*8 + i;
        #pragma unroll
        for (int j = 0; j < 8; j += 4) {
            const int c = col0 + tx*8 + j;
            float4 o;
            o.x = acc[i][j+0] + bv[c+0];
            o.y = acc[i][j+1] + bv[c+1];
            o.z = acc[i][j+2] + bv[c+2];
            o.w = acc[i][j+3] + bv[c+3];
            *(float4*)&g_v[(size_t)r*DIM + c] = o;
        }
    }
}

__device__ __forceinline__ void score_path(char* smraw, int b)
{
    const int tid = threadIdx.x;
    const int tx = tid & 15, ty = tid >> 4;
    int* As8 = (int*)smraw;          // [2][8*128]
    int* Bs8 = (int*)smraw + 2048;

    const int k0t = blockIdx.x * 128;
    const int q0t = blockIdx.y * 128;
    const uint32_t* q8 = g_q8 + (size_t)b*SEQ*(DIM/4);
    const uint32_t* k8 = g_k8 + (size_t)b*SEQ*(DIM/4);

    int acc[8][8];
    #pragma unroll
    for (int i = 0; i < 8; i++)
        #pragma unroll
        for (int j = 0; j < 8; j++) acc[i][j] = 0;

    const int amm = tid >> 1;
    const int au  = (tid & 1) * 4;

    const int NST = 8;
    uint4 rA, rB;

    rA = *(const uint4*)&q8[(size_t)(q0t + amm)*(DIM/4) + au];
    rB = *(const uint4*)&k8[(size_t)(k0t + amm)*(DIM/4) + au];
    As8[(au+0)*128 + amm] = (int)rA.x;
    As8[(au+1)*128 + amm] = (int)rA.y;
    As8[(au+2)*128 + amm] = (int)rA.z;
    As8[(au+3)*128 + amm] = (int)rA.w;
    Bs8[(au+0)*128 + amm] = (int)rB.x;
    Bs8[(au+1)*128 + amm] = (int)rB.y;
    Bs8[(au+2)*128 + amm] = (int)rB.z;
    Bs8[(au+3)*128 + amm] = (int)rB.w;
    __syncthreads();

    for (int s = 0; s < NST; s++) {
        if (s + 1 < NST) {
            rA = *(const uint4*)&q8[(size_t)(q0t + amm)*(DIM/4) + (s+1)*8 + au];
            rB = *(const uint4*)&k8[(size_t)(k0t + amm)*(DIM/4) + (s+1)*8 + au];
        }
        const int* Ac = As8 + (s & 1)*1024;
        const int* Bc = Bs8 + (s & 1)*1024;
        #pragma unroll
        for (int pk = 0; pk < 8; pk++) {
            int a[8], bb[8];
            *(int4*)&a[0]  = *(const int4*)&Ac[pk*128 + ty*8];
            *(int4*)&a[4]  = *(const int4*)&Ac[pk*128 + ty*8 + 4];
            *(int4*)&bb[0] = *(const int4*)&Bc[pk*128 + tx*8];
            *(int4*)&bb[4] = *(const int4*)&Bc[pk*128 + tx*8 + 4];
            #pragma unroll
            for (int i = 0; i < 8; i++)
                #pragma unroll
                for (int j = 0; j < 8; j++)
                    acc[i][j] = __dp4a(a[i], bb[j], acc[i][j]);
        }
        if (s + 1 < NST) {
            int* An = As8 + ((s+1) & 1)*1024;
            int* Bn = Bs8 + ((s+1) & 1)*1024;
            An[(au+0)*128 + amm] = (int)rA.x;
            An[(au+1)*128 + amm] = (int)rA.y;
            An[(au+2)*128 + amm] = (int)rA.z;
            An[(au+3)*128 + amm] = (int)rA.w;
            Bn[(au+0)*128 + amm] = (int)rB.x;
            Bn[(au+1)*128 + amm] = (int)rB.y;
            Bn[(au+2)*128 + amm] = (int)rB.z;
            Bn[(au+3)*128 + amm] = (int)rB.w;
            __syncthreads();
        }
    }

    short* srow = g_ss + ((size_t)b*SEQ + q0t)*SEQ + k0t;
    #pragma unroll
    for (int i = 0; i < 8; i++) {
        uint32_t w[4];
        #pragma unroll
        for (int j2 = 0; j2 < 4; j2++) {
            int v0 = acc[i][j2*2+0], v1 = acc[i][j2*2+1];
            v0 = v0 > 32767 ? 32767 : (v0 < -32768 ? -32768 : v0);
            v1 = v1 > 32767 ? 32767 : (v1 < -32768 ? -32768 : v1);
            w[j2] = (uint32_t)(v0 & 0xffff) | ((uint32_t)v1 << 16);
        }
        *(uint4*)&srow[(size_t)(ty*8 + i)*SEQ + tx*8] = *(uint4*)w;
    }
}

__device__ __forceinline__ void select_path(int b, float* __restrict__ out)
{
    const int tid  = threadIdx.x;
    const int cidx = blockIdx.y * 32 + blockIdx.x;
    if (cidx >= 512) return;                 // 512 live CTAs, 8 queries each
    const int lane = tid & 31;
    const int q    = cidx * 8 + (tid >> 5);

    int myval = INT_MIN;
    int myidx = 0;

    const uint4* srow = (const uint4*)(g_ss + ((size_t)b*SEQ + q)*SEQ);

    uint4 u = __ldcs(&srow[lane]);
    #pragma unroll 1
    for (int i = 0; i < SEQ/256; i++) {
        uint4 cur = u;
        if (i + 1 < SEQ/256)
            u = __ldcs(&srow[(i+1)*32 + lane]);
        int sv[8];
        sv[0] = (int)(short)(cur.x);  sv[1] = (int)(short)(cur.x >> 16);
        sv[2] = (int)(short)(cur.y);  sv[3] = (int)(short)(cur.y >> 16);
        sv[4] = (int)(short)(cur.z);  sv[5] = (int)(short)(cur.z >> 16);
        sv[6] = (int)(short)(cur.w);  sv[7] = (int)(short)(cur.w >> 16);
        int thr = __shfl_sync(FULLM, myval, 31);
        bool cand = false;
        #pragma unroll
        for (int t = 0; t < 8; t++) cand |= (sv[t] > thr);
        if (__any_sync(FULLM, cand)) {
            #pragma unroll
            for (int t = 0; t < 8; t++) {
                int v = sv[t];
                thr = __shfl_sync(FULLM, myval, 31);
                unsigned cm = __ballot_sync(FULLM, v > thr);
                while (cm) {
                    int src = __ffs(cm) - 1;
                    cm &= cm - 1;
                    int bv2  = __shfl_sync(FULLM, v, src);
                    int bidx = i*256 + src*8 + t;
                    bool gt = bv2 > myval;
                    unsigned bm = __ballot_sync(FULLM, gt);
                    int upv = __shfl_up_sync(FULLM, myval, 1);
                    int upi = __shfl_up_sync(FULLM, myidx, 1);
                    if (bm) {
                        int p = __ffs(bm) - 1;
                        if (gt) {
                            myval = (lane == p) ? bv2 : upv;
                            myidx = (lane == p) ? bidx : upi;
                        }
                    }
                }
            }
        }
    }

    // exact fp32 rescore of the 32 selected keys
    const float4* qr = (const float4*)(g_q + ((size_t)b*SEQ + q)*DIM);
    float4 q0v = qr[lane*2], q1v = qr[lane*2 + 1];
    float myex = 0.f;
    #pragma unroll 4
    for (int j = 0; j < TOPK; j++) {
        int ij = __shfl_sync(FULLM, myidx, j);
        const float4* kr = (const float4*)(g_k + ((size_t)b*SEQ + ij)*DIM);
        float4 k0v = kr[lane*2], k1v = kr[lane*2 + 1];
        float d = q0v.x*k0v.x;
        d = fmaf(q0v.y, k0v.y, d);
        d = fmaf(q0v.z, k0v.z, d);
        d = fmaf(q0v.w, k0v.w, d);
        d = fmaf(q1v.x, k1v.x, d);
        d = fmaf(q1v.y, k1v.y, d);
        d = fmaf(q1v.z, k1v.z, d);
        d = fmaf(q1v.w, k1v.w, d);
        #pragma unroll
        for (int o = 16; o; o >>= 1) d += __shfl_xor_sync(FULLM, d, o);
        if (lane == j) myex = d;
    }

    float mx = myex;
    #pragma unroll
    for (int o = 16; o; o >>= 1) mx = fmaxf(mx, __shfl_xor_sync(FULLM, mx, o));
    float e = expf(myex - mx);
    float ssum = e;
    #pragma unroll
    for (int o = 16; o; o >>= 1) ssum += __shfl_xor_sync(FULLM, ssum, o);
    float p = e / ssum;

    const float4* vb = (const float4*)(g_v + (size_t)b*SEQ*DIM);
    float4 a0 = make_float4(0.f,0.f,0.f,0.f);
    float4 a1 = make_float4(0.f,0.f,0.f,0.f);
    #pragma unroll 4
    for (int j = 0; j < TOPK; j++) {
        float pj = __shfl_sync(FULLM, p, j);
        int   ij = __shfl_sync(FULLM, myidx, j);
        float4 v0 = vb[(size_t)ij*64 + lane*2];
        float4 v1 = vb[(size_t)ij*64 + lane*2 + 1];
        a0.x = fmaf(pj, v0.x, a0.x);
        a0.y = fmaf(pj, v0.y, a0.y);
        a0.z = fmaf(pj, v0.z, a0.z);
        a0.w = fmaf(pj, v0.w, a0.w);
        a1.x = fmaf(pj, v1.x, a1.x);
        a1.y = fmaf(pj, v1.y, a1.y);
        a1.z = fmaf(pj, v1.z, a1.z);
        a1.w = fmaf(pj, v1.w, a1.w);
    }
    float4* ob = (float4*)(out + ((size_t)b*SEQ + q)*DIM);
    ob[lane*2]     = a0;
    ob[lane*2 + 1] = a1;
}

// ---------------------------------------------------------------------------
// Phase kernels (no runtime sync; dependencies via launch boundaries)
// ---------------------------------------------------------------------------
// A: z=0 vproj, z=1 scores b0, z=2 scores b1
__global__ __launch_bounds__(256, 2)
void phaseA_kernel(const float* __restrict__ x,
                   const float* __restrict__ Wv, const float* __restrict__ bv)
{
    __shared__ __align__(16) char smraw[16384];
    if (blockIdx.z == 0) vproj_path(smraw, x, Wv, bv);
    else                 score_path(smraw, blockIdx.z - 1);
}

// B: z=0 scores b2, z=1 scores b3, z=2 select b0, z=3 select b1
__global__ __launch_bounds__(256, 2)
void phaseB_kernel(float* __restrict__ out)
{
    __shared__ __align__(16) char smraw[16384];
    if (blockIdx.z < 2) score_path(smraw, 2 + blockIdx.z);
    else                select_path(blockIdx.z - 2, out);
}

// C: z=0 select b2, z=1 select b3
__global__ __launch_bounds__(256, 2)
void phaseC_kernel(float* __restrict__ out)
{
    select_path(2 + blockIdx.z, out);
}

extern "C" void kernel_launch(void* const* d_in, const int* in_sizes, int n_in,
                              void* d_out, int out_size)
{
    const float* x  = (const float*)d_in[0];
    const float* Wq = (const float*)d_in[1];
    const float* bq = (const float*)d_in[2];
    const float* Wk = (const float*)d_in[3];
    const float* bk = (const float*)d_in[4];
    const float* Wv = (const float*)d_in[5];
    const float* bv = (const float*)d_in[6];
    float* out = (float*)d_out;

    dim3 g1(ROWS/128, DIM/128, 2);            // q,k only
    qkv_kernel<<<g1, 256>>>(x, Wq, bq, Wk, bk);

    dim3 gA(32, 32, 3);
    phaseA_kernel<<<gA, 256>>>(x, Wv, bv);

    dim3 gB(32, 32, 4);
    phaseB_kernel<<<gB, 256>>>(out);

    dim3 gC(32, 32, 2);
    phaseC_kernel<<<gC, 256>>>(out);
}